// round 15
// baseline (speedup 1.0000x reference)
#include <cuda_runtime.h>
#include <cuda_bf16.h>
#include <cstdint>

// Problem dimensions (fixed by setup_inputs)
#define BB 9600      // batch rows (Z)
#define BBPAD 9728   // padded to multiple of 256
#define SS 2400      // candidate rows (Y)
#define SPAD 2432    // S padded to multiple of 128
#define FF 4096      // feature dim
#define BK 64        // K elems per pipeline chunk
#define NCH (FF / BK)  // 64 chunks

#define AMAX 512         // ambiguous-col capacity per row (overflow -> full recount)
#define DELTA 3e-4f      // 6-sigma filter window for hh-only bf16 sims

// ---------------------------------------------------------------------------
// Scratch (device globals: allocation-free rule).
__device__ __nv_bfloat16 g_Zh[(size_t)BBPAD * FF];
__device__ __nv_bfloat16 g_Yh[(size_t)SPAD * FF];
__device__ float g_Znorm[BB];
__device__ float g_Ynorm[SS];
__device__ float g_simL[BB];
__device__ int   g_labels[BB];
__device__ int   g_inv[SS];
__device__ int   g_gt[BB];       // definite + rescored counts
__device__ int   g_rankovf[BB];  // full recount for overflow rows
__device__ int   g_ambcnt[BB];
__device__ int   g_ambcol[(size_t)BB * AMAX];
__device__ int   g_hit[2];

// ---------------------------------------------------------------------------
// Launch 1: zero counters + scatter inverse map (test values unique per spec).
__global__ void init_scatter_kernel(const int* __restrict__ test) {
    int i = blockIdx.x * blockDim.x + threadIdx.x;
    if (i < BB) { g_gt[i] = 0; g_rankovf[i] = 0; g_ambcnt[i] = 0; }
    if (i < 2)  g_hit[i] = 0;
    if (i < SS) {
        int v = test[i];
        if (v >= 0 && v < SS) g_inv[v] = i;
    }
}

__device__ __forceinline__ uint32_t pack_bf2(__nv_bfloat16 a, __nv_bfloat16 b) {
    __nv_bfloat162 t = __halves2bfloat162(a, b);
    return *reinterpret_cast<uint32_t*>(&t);
}

// Launch 2: normalize row -> bf16 high part + fp32 norm. Covers Z (padded) and Y.
__global__ void norm_split_kernel(const float* __restrict__ Zsrc,
                                  const float* __restrict__ Ysrc) {
    int row = blockIdx.x;
    int tid = threadIdx.x;  // 128 threads
    const float* src;
    __nv_bfloat16* H;
    int which, realrows;
    if (row < BBPAD) {
        src = Zsrc; H = g_Zh; which = 0; realrows = BB;
    } else {
        row -= BBPAD;
        src = Ysrc; H = g_Yh; which = 1; realrows = SS;
    }
    size_t base = (size_t)row * FF;

    if (row >= realrows) {  // zero padding rows
        for (int j = 0; j < 8; j++)
            *(uint2*)(H + base + tid * 4 + j * 512) = make_uint2(0, 0);
        return;
    }

    float4 v[8];
    float s = 0.f;
#pragma unroll
    for (int j = 0; j < 8; j++) {
        v[j] = *(const float4*)(src + base + tid * 4 + j * 512);
        s += v[j].x * v[j].x + v[j].y * v[j].y + v[j].z * v[j].z + v[j].w * v[j].w;
    }
    for (int o = 16; o > 0; o >>= 1) s += __shfl_xor_sync(0xffffffffu, s, o);
    __shared__ float red[4];
    __shared__ float s_n;
    if ((tid & 31) == 0) red[tid >> 5] = s;
    __syncthreads();
    if (tid == 0) {
        float t = red[0] + red[1] + red[2] + red[3];
        s_n = fmaxf(sqrtf(t), 1e-8f);
        if (which == 0) g_Znorm[row] = s_n;
        else            g_Ynorm[row] = s_n;
    }
    __syncthreads();
    float n = s_n;

#pragma unroll
    for (int j = 0; j < 8; j++) {
        size_t off = base + tid * 4 + j * 512;
        float x[4] = {v[j].x / n, v[j].y / n, v[j].z / n, v[j].w / n};
        __nv_bfloat16 h[4];
#pragma unroll
        for (int e = 0; e < 4; e++) h[e] = __float2bfloat16(x[e]);
        *(uint2*)(H + off) = make_uint2(pack_bf2(h[0], h[1]), pack_bf2(h[2], h[3]));
    }
}

// Launch 3: labels[i] = inv[yidx[i]]; simL[i] = cos-sim(Z[i], Y[lab]) in fp32.
__global__ void labels_simL_kernel(const float* __restrict__ Z,
                                   const float* __restrict__ Y,
                                   const int* __restrict__ yidx) {
    int i = blockIdx.x;
    int tid = threadIdx.x;  // 128
    __shared__ int s_lab;
    if (tid == 0) {
        int v = yidx[i];
        int lab = 0;
        if (v >= 0 && v < SS) lab = g_inv[v];
        g_labels[i] = lab;
        s_lab = lab;
    }
    __syncthreads();
    int lab = s_lab;
    const float* z = Z + (size_t)i * FF;
    const float* y = Y + (size_t)lab * FF;
    float s = 0.f;
    for (int c = tid * 4; c < FF; c += 512) {
        float4 a = *(const float4*)(z + c);
        float4 b = *(const float4*)(y + c);
        s += a.x * b.x + a.y * b.y + a.z * b.z + a.w * b.w;
    }
    for (int o = 16; o > 0; o >>= 1) s += __shfl_xor_sync(0xffffffffu, s, o);
    __shared__ float red[4];
    if ((tid & 31) == 0) red[tid >> 5] = s;
    __syncthreads();
    if (tid == 0) {
        float t = red[0] + red[1] + red[2] + red[3];
        g_simL[i] = t / (g_Znorm[i] * g_Ynorm[lab]);
    }
}

// ---------------------------------------------------------------------------
// Launch 4: warp-specialized bf16 HMMA filter GEMM (Ah*Bh only) + threshold
// epilogue. 256x128 CTA tile, BK=64, 4-stage mbarrier ring, 8 consumer warps
// (64x64 tiles, 4x2) + 1 producer warp (288 threads).
#define A_TILE_B 32768               // 256 rows x 128B
#define B_TILE_B 16384               // 128 rows x 128B
#define STAGE_B  (A_TILE_B + B_TILE_B)  // 48 KB
#define OFF_B    A_TILE_B
#define NST 4
#define SMEM_DYN (NST * STAGE_B)     // 192 KB

// 128B-row swizzle: row r, 16B-chunk c (0..7)
__device__ __forceinline__ uint32_t swz8(int r, int c) {
    return (uint32_t)(r * 128 + ((c ^ (r & 7)) << 4));
}

static __device__ __forceinline__ uint32_t cvta_s(const void* p) {
    uint32_t a;
    asm("{ .reg .u64 t; cvta.to.shared.u64 t, %1; cvt.u32.u64 %0, t; }" : "=r"(a) : "l"(p));
    return a;
}

__device__ __forceinline__ void ldsm_x4(uint32_t* r, uint32_t addr) {
    asm volatile("ldmatrix.sync.aligned.m8n8.x4.shared.b16 {%0,%1,%2,%3}, [%4];"
                 : "=r"(r[0]), "=r"(r[1]), "=r"(r[2]), "=r"(r[3]) : "r"(addr));
}

__device__ __forceinline__ void mma16816(float* c, const uint32_t* a, uint32_t b0, uint32_t b1) {
    asm volatile(
        "mma.sync.aligned.m16n8k16.row.col.f32.bf16.bf16.f32 "
        "{%0,%1,%2,%3}, {%4,%5,%6,%7}, {%8,%9}, {%0,%1,%2,%3};"
        : "+f"(c[0]), "+f"(c[1]), "+f"(c[2]), "+f"(c[3])
        : "r"(a[0]), "r"(a[1]), "r"(a[2]), "r"(a[3]), "r"(b0), "r"(b1));
}

__device__ __forceinline__ void mbar_wait(uint32_t mbar, uint32_t parity) {
    uint32_t done;
    asm volatile(
        "{\n\t.reg .pred p;\n\t"
        "mbarrier.try_wait.parity.shared.b64 p, [%1], %2;\n\t"
        "selp.b32 %0, 1, 0, p;\n\t}"
        : "=r"(done) : "r"(mbar), "r"(parity) : "memory");
    if (!done) {
        asm volatile(
            "{\n\t.reg .pred P1;\n\t"
            "WL_%=:\n\t"
            "mbarrier.try_wait.parity.shared.b64 P1, [%0], %1;\n\t"
            "@P1 bra.uni WD_%=;\n\t"
            "bra.uni WL_%=;\n\t"
            "WD_%=:\n\t}"
            :: "r"(mbar), "r"(parity) : "memory");
    }
}

extern __shared__ char dsm[];

__global__ __launch_bounds__(288, 1) void gemm_count_kernel() {
    __shared__ __align__(8) unsigned long long s_mb[2 * NST];
    int tid = threadIdx.x;
    int lane = tid & 31, wid = tid >> 5;
    int brow = blockIdx.y * 256;
    int bcol = blockIdx.x * 128;
    uint32_t smem = cvta_s(dsm);
    uint32_t mb0 = cvta_s(&s_mb[0]);

    if (tid == 0) {
#pragma unroll
        for (int s = 0; s < NST; s++) {
            asm volatile("mbarrier.init.shared.b64 [%0], 32;" :: "r"(mb0 + s * 16) : "memory");
            asm volatile("mbarrier.init.shared.b64 [%0], 8;"  :: "r"(mb0 + s * 16 + 8) : "memory");
        }
    }
    __syncthreads();  // only block-wide barrier

    if (wid == 8) {
        // Producer. pe starts at 1 (flipped at wrap after chunk NST-1 so the
        // first recycle-wait sees parity 0 = chunk-0 consumption).
        const __nv_bfloat16* pA = g_Zh + (size_t)brow * FF;
        const __nv_bfloat16* pB = g_Yh + (size_t)bcol * FF;
        int s = 0, pe = 1;
        for (int c = 0; c < NCH; c++) {
            if (c >= NST) mbar_wait(mb0 + s * 16 + 8, (uint32_t)pe);  // empty[s]
            uint32_t stagebase = smem + s * STAGE_B;
            {
                const __nv_bfloat16* sb = pA + c * BK;
#pragma unroll
                for (int j = 0; j < 64; j++) {  // A: 256 rows x 8 chunks = 2048 units
                    int idx = lane + j * 32;
                    int r = idx >> 3, ck = idx & 7;
                    const void* src = sb + (size_t)r * FF + ck * 8;
                    uint32_t dst = stagebase + swz8(r, ck);
                    asm volatile("cp.async.cg.shared.global [%0], [%1], 16;"
                                 :: "r"(dst), "l"(src));
                }
            }
            {
                const __nv_bfloat16* sb = pB + c * BK;
#pragma unroll
                for (int j = 0; j < 32; j++) {  // B: 128 rows x 8 chunks = 1024 units
                    int idx = lane + j * 32;
                    int r = idx >> 3, ck = idx & 7;
                    const void* src = sb + (size_t)r * FF + ck * 8;
                    uint32_t dst = stagebase + OFF_B + swz8(r, ck);
                    asm volatile("cp.async.cg.shared.global [%0], [%1], 16;"
                                 :: "r"(dst), "l"(src));
                }
            }
            asm volatile("cp.async.mbarrier.arrive.noinc.shared.b64 [%0];"
                         :: "r"(mb0 + s * 16) : "memory");
            s++; if (s == NST) { s = 0; pe ^= 1; }
        }
        return;
    }

    // Consumers: 8 warps, 64x64 tiles (warp_m 0..3, warp_n 0..1).
    int warp_m = wid & 3;
    int warp_n = wid >> 2;

    float acc[4][8][4];
#pragma unroll
    for (int i = 0; i < 4; i++)
#pragma unroll
        for (int j = 0; j < 8; j++)
#pragma unroll
            for (int v = 0; v < 4; v++) acc[i][j][v] = 0.f;

    int a_r = warp_m * 64 + (lane & 15);   // + i*16
    int b_r = warp_n * 64 + (lane & 15);   // + g*16
    int csel = lane >> 4;                  // 16B chunk within k16: + ks*2

    uint32_t fa[4][4], fb[4][4];

    int st = 0, pf = 0;
    for (int c = 0; c < NCH; c++) {
        mbar_wait(mb0 + st * 16, (uint32_t)pf);  // full[st]
        uint32_t buf = smem + st * STAGE_B;

#pragma unroll
        for (int ks = 0; ks < 4; ks++) {
#pragma unroll
            for (int i = 0; i < 4; i++)
                ldsm_x4(fa[i], buf + swz8(a_r + i * 16, ks * 2 + csel));
#pragma unroll
            for (int g = 0; g < 4; g++)
                ldsm_x4(fb[g], buf + OFF_B + swz8(b_r + g * 16, ks * 2 + csel));
#pragma unroll
            for (int i = 0; i < 4; i++)
#pragma unroll
                for (int jj = 0; jj < 8; jj++) {
                    int g = jj >> 1, w = jj & 1;
                    mma16816(acc[i][jj], fa[i], fb[g][w], fb[g][2 + w]);
                }
        }

        if (lane == 0)
            asm volatile("mbarrier.arrive.shared.b64 _, [%0];"
                         :: "r"(mb0 + st * 16 + 8) : "memory");  // empty[st]
        st++; if (st == NST) { st = 0; pf ^= 1; }
    }

    // Epilogue: threshold filter. Definite gt counted; near-threshold cols
    // pushed for exact fp32 rescore. Rows >= BB are padding (skipped).
#pragma unroll
    for (int i = 0; i < 4; i++) {
#pragma unroll
        for (int h = 0; h < 2; h++) {
            int row = brow + warp_m * 64 + i * 16 + (lane >> 2) + h * 8;
            if (row >= BB) continue;
            float sl = g_simL[row];
            int lab = g_labels[row];
            int gt = 0;
#pragma unroll
            for (int jj = 0; jj < 8; jj++) {
#pragma unroll
                for (int w = 0; w < 2; w++) {
                    int col = bcol + warp_n * 64 + jj * 8 + (lane & 3) * 2 + w;
                    float v = acc[i][jj][h * 2 + w];
                    if (col < SS && col != lab) {
                        if (v > sl + DELTA) gt++;
                        else if (v >= sl - DELTA) {
                            int idx = atomicAdd(&g_ambcnt[row], 1);
                            if (idx < AMAX) g_ambcol[(size_t)row * AMAX + idx] = col;
                        }
                    }
                }
            }
            gt += __shfl_xor_sync(0xffffffffu, gt, 1);
            gt += __shfl_xor_sync(0xffffffffu, gt, 2);
            if ((lane & 3) == 0 && gt) atomicAdd(&g_gt[row], gt);
        }
    }
}

// ---------------------------------------------------------------------------
// Launch 5: exact fp32 rescore of ambiguous cols. One block per row.
// Overflow rows (> AMAX ambiguous) get a deterministic full recount.
__global__ __launch_bounds__(256) void rescore_kernel(const float* __restrict__ Z,
                                                      const float* __restrict__ Y) {
    int row = blockIdx.x;
    int tid = threadIdx.x, lane = tid & 31, wrp = tid >> 5;
    int cnt = g_ambcnt[row];
    if (cnt == 0) return;
    bool ovf = cnt > AMAX;
    int n = ovf ? SS : cnt;

    __shared__ float zs[FF];
    const float* z = Z + (size_t)row * FF;
    for (int c = tid * 4; c < FF; c += 1024)
        *(float4*)(zs + c) = *(const float4*)(z + c);
    __syncthreads();

    float sl = g_simL[row];
    int lab = g_labels[row];
    float zn = g_Znorm[row];

    int gt = 0;
    for (int k = wrp; k < n; k += 8) {
        int col = ovf ? k : g_ambcol[(size_t)row * AMAX + k];
        if (col == lab || col >= SS) continue;
        const float* y = Y + (size_t)col * FF;
        float s = 0.f;
#pragma unroll 4
        for (int c = lane * 4; c < FF; c += 128) {
            float4 a = *(const float4*)(zs + c);
            float4 b = *(const float4*)(y + c);
            s += a.x * b.x + a.y * b.y + a.z * b.z + a.w * b.w;
        }
        for (int o = 16; o > 0; o >>= 1) s += __shfl_xor_sync(0xffffffffu, s, o);
        if (lane == 0) {
            float v = s / (zn * g_Ynorm[col]);
            if (v > sl) gt++;
            else if (v == sl && col < lab) gt++;
        }
    }
    if (lane == 0 && gt) {
        if (ovf) atomicAdd(&g_rankovf[row], gt);
        else     atomicAdd(&g_gt[row], gt);
    }
}

// ---------------------------------------------------------------------------
__global__ void finalize_kernel() {
    int i = blockIdx.x * blockDim.x + threadIdx.x;
    if (i >= BB) return;
    int r = (g_ambcnt[i] > AMAX) ? g_rankovf[i] : g_gt[i];
    if (r < 1) atomicAdd(&g_hit[0], 1);
    if (r < 5) atomicAdd(&g_hit[1], 1);
}

__global__ void writeout_kernel(float* __restrict__ out) {
    out[0] = (float)g_hit[0] / (float)BB;
    out[1] = (float)g_hit[1] / (float)BB;
}

// ---------------------------------------------------------------------------
extern "C" void kernel_launch(void* const* d_in, const int* in_sizes, int n_in,
                              void* d_out, int out_size) {
    (void)in_sizes; (void)n_in; (void)out_size;
    const float* Z    = (const float*)d_in[0];
    const int*   yidx = (const int*)d_in[1];
    const float* Y    = (const float*)d_in[2];
    const int*   test = (const int*)d_in[3];
    float* out = (float*)d_out;

    cudaFuncSetAttribute(gemm_count_kernel,
                         cudaFuncAttributeMaxDynamicSharedMemorySize, SMEM_DYN);

    init_scatter_kernel<<<(BB + 255) / 256, 256>>>(test);      // launch 1
    norm_split_kernel<<<BBPAD + SPAD, 128>>>(Z, Y);            // launch 2
    labels_simL_kernel<<<BB, 128>>>(Z, Y, yidx);               // launch 3

    dim3 grid(SPAD / 128, BBPAD / 256);
    gemm_count_kernel<<<grid, 288, SMEM_DYN>>>();              // launch 4 (ncu target)

    rescore_kernel<<<BB, 256>>>(Z, Y);                         // launch 5
    finalize_kernel<<<(BB + 255) / 256, 256>>>();              // launch 6
    writeout_kernel<<<1, 1>>>(out);                            // launch 7
}

// round 16
// speedup vs baseline: 1.2778x; 1.2778x over previous
#include <cuda_runtime.h>
#include <cuda_fp16.h>
#include <cstdint>

// Problem dimensions (fixed by setup_inputs)
#define BB 9600      // batch rows (Z)
#define SS 2400      // candidate rows (Y)
#define SPAD 2432    // S padded to multiple of 128
#define FF 4096      // feature dim
#define NCH (FF / 32)  // 32-elem K chunks for GEMM

#define AMAX 512         // ambiguous-col capacity per row (overflow -> full recount)
#define DELTA 1e-4f      // >=12-sigma filter window for fp16 sims

// ---------------------------------------------------------------------------
// Scratch (device globals: allocation-free rule). fp16 high parts.
__device__ __half g_Zh[(size_t)BB * FF];
__device__ __half g_Yh[(size_t)SPAD * FF];
__device__ float g_Znorm[BB];
__device__ float g_Ynorm[SS];
__device__ float g_simL[BB];
__device__ int   g_labels[BB];
__device__ int   g_inv[SS];
__device__ int   g_gt[BB];       // definite + rescored counts
__device__ int   g_ambcnt[BB];
__device__ int   g_ambcol[(size_t)BB * AMAX];
__device__ int   g_hit[2];

// ---------------------------------------------------------------------------
// Launch 1: zero counters + scatter inverse map (test values unique per spec).
__global__ void init_scatter_kernel(const int* __restrict__ test) {
    int i = blockIdx.x * blockDim.x + threadIdx.x;
    if (i < BB) { g_gt[i] = 0; g_ambcnt[i] = 0; }
    if (i < 2)  g_hit[i] = 0;
    if (i < SS) {
        int v = test[i];
        if (v >= 0 && v < SS) g_inv[v] = i;
    }
}

__device__ __forceinline__ uint32_t pack_h2(__half a, __half b) {
    __half2 t = __halves2half2(a, b);
    return *reinterpret_cast<uint32_t*>(&t);
}

// Launch 2: normalize row -> fp16 high part + fp32 norm. Covers Z and Y.
__global__ void norm_split_kernel(const float* __restrict__ Zsrc,
                                  const float* __restrict__ Ysrc) {
    int row = blockIdx.x;
    int tid = threadIdx.x;  // 128 threads
    const float* src;
    __half* H;
    int which;
    if (row < BB) {
        src = Zsrc; H = g_Zh; which = 0;
    } else {
        row -= BB;
        src = Ysrc; H = g_Yh; which = 1;
    }
    size_t base = (size_t)row * FF;

    if (which == 1 && row >= SS) {  // zero padding rows (Y only)
        for (int j = 0; j < 8; j++)
            *(uint2*)(H + base + tid * 4 + j * 512) = make_uint2(0, 0);
        return;
    }

    float4 v[8];
    float s = 0.f;
#pragma unroll
    for (int j = 0; j < 8; j++) {
        v[j] = *(const float4*)(src + base + tid * 4 + j * 512);
        s += v[j].x * v[j].x + v[j].y * v[j].y + v[j].z * v[j].z + v[j].w * v[j].w;
    }
    for (int o = 16; o > 0; o >>= 1) s += __shfl_xor_sync(0xffffffffu, s, o);
    __shared__ float red[4];
    __shared__ float s_n;
    if ((tid & 31) == 0) red[tid >> 5] = s;
    __syncthreads();
    if (tid == 0) {
        float t = red[0] + red[1] + red[2] + red[3];
        s_n = fmaxf(sqrtf(t), 1e-8f);
        if (which == 0) g_Znorm[row] = s_n;
        else            g_Ynorm[row] = s_n;
    }
    __syncthreads();
    float n = s_n;

#pragma unroll
    for (int j = 0; j < 8; j++) {
        size_t off = base + tid * 4 + j * 512;
        float x[4] = {v[j].x / n, v[j].y / n, v[j].z / n, v[j].w / n};
        __half h[4];
#pragma unroll
        for (int e = 0; e < 4; e++) h[e] = __float2half(x[e]);
        *(uint2*)(H + off) = make_uint2(pack_h2(h[0], h[1]), pack_h2(h[2], h[3]));
    }
}

// Launch 3: labels[i] = inv[yidx[i]]; simL[i] = cos-sim(Z[i], Y[lab]) in fp32.
__global__ void labels_simL_kernel(const float* __restrict__ Z,
                                   const float* __restrict__ Y,
                                   const int* __restrict__ yidx) {
    int i = blockIdx.x;
    int tid = threadIdx.x;  // 128
    __shared__ int s_lab;
    if (tid == 0) {
        int v = yidx[i];
        int lab = 0;
        if (v >= 0 && v < SS) lab = g_inv[v];
        g_labels[i] = lab;
        s_lab = lab;
    }
    __syncthreads();
    int lab = s_lab;
    const float* z = Z + (size_t)i * FF;
    const float* y = Y + (size_t)lab * FF;
    float s = 0.f;
    for (int c = tid * 4; c < FF; c += 512) {
        float4 a = *(const float4*)(z + c);
        float4 b = *(const float4*)(y + c);
        s += a.x * b.x + a.y * b.y + a.z * b.z + a.w * b.w;
    }
    for (int o = 16; o > 0; o >>= 1) s += __shfl_xor_sync(0xffffffffu, s, o);
    __shared__ float red[4];
    if ((tid & 31) == 0) red[tid >> 5] = s;
    __syncthreads();
    if (tid == 0) {
        float t = red[0] + red[1] + red[2] + red[3];
        g_simL[i] = t / (g_Znorm[i] * g_Ynorm[lab]);
    }
}

// ---------------------------------------------------------------------------
// Launch 4: warp-specialized fp16 HMMA filter GEMM + threshold epilogue.
// 192x128 CTA tile, BK=32, 8-stage mbarrier ring, 12 consumer warps
// + 1 producer warp (416 threads).  [exact R14 structure, fp16 operands]
#define A_TILE_B 12288               // 192 rows x 64B
#define B_TILE_B 8192                // 128 rows x 64B
#define STAGE_B  (A_TILE_B + B_TILE_B)  // 20 KB
#define OFF_B    A_TILE_B
#define NST 8
#define SMEM_DYN (NST * STAGE_B)     // 160 KB

// 64B-row swizzle: row r, 16B-chunk c (0..3)
__device__ __forceinline__ uint32_t swz(int r, int c) {
    return (uint32_t)(r * 64 + ((c ^ ((r >> 1) & 3)) << 4));
}

static __device__ __forceinline__ uint32_t cvta_s(const void* p) {
    uint32_t a;
    asm("{ .reg .u64 t; cvta.to.shared.u64 t, %1; cvt.u32.u64 %0, t; }" : "=r"(a) : "l"(p));
    return a;
}

__device__ __forceinline__ void ldsm_x4(uint32_t* r, uint32_t addr) {
    asm volatile("ldmatrix.sync.aligned.m8n8.x4.shared.b16 {%0,%1,%2,%3}, [%4];"
                 : "=r"(r[0]), "=r"(r[1]), "=r"(r[2]), "=r"(r[3]) : "r"(addr));
}

__device__ __forceinline__ void mma16816(float* c, const uint32_t* a, uint32_t b0, uint32_t b1) {
    asm volatile(
        "mma.sync.aligned.m16n8k16.row.col.f32.f16.f16.f32 "
        "{%0,%1,%2,%3}, {%4,%5,%6,%7}, {%8,%9}, {%0,%1,%2,%3};"
        : "+f"(c[0]), "+f"(c[1]), "+f"(c[2]), "+f"(c[3])
        : "r"(a[0]), "r"(a[1]), "r"(a[2]), "r"(a[3]), "r"(b0), "r"(b1));
}

__device__ __forceinline__ void mbar_wait(uint32_t mbar, uint32_t parity) {
    uint32_t done;
    asm volatile(
        "{\n\t.reg .pred p;\n\t"
        "mbarrier.try_wait.parity.shared.b64 p, [%1], %2;\n\t"
        "selp.b32 %0, 1, 0, p;\n\t}"
        : "=r"(done) : "r"(mbar), "r"(parity) : "memory");
    if (!done) {
        asm volatile(
            "{\n\t.reg .pred P1;\n\t"
            "WL_%=:\n\t"
            "mbarrier.try_wait.parity.shared.b64 P1, [%0], %1;\n\t"
            "@P1 bra.uni WD_%=;\n\t"
            "bra.uni WL_%=;\n\t"
            "WD_%=:\n\t}"
            :: "r"(mbar), "r"(parity) : "memory");
    }
}

extern __shared__ char dsm[];

__global__ __launch_bounds__(416, 1) void gemm_count_kernel() {
    __shared__ __align__(8) unsigned long long s_mb[2 * NST];
    int tid = threadIdx.x;
    int lane = tid & 31, wid = tid >> 5;
    int brow = blockIdx.y * 192;
    int bcol = blockIdx.x * 128;
    uint32_t smem = cvta_s(dsm);
    uint32_t mb0 = cvta_s(&s_mb[0]);

    if (tid == 0) {
#pragma unroll
        for (int s = 0; s < NST; s++) {
            asm volatile("mbarrier.init.shared.b64 [%0], 32;" :: "r"(mb0 + s * 16) : "memory");
            asm volatile("mbarrier.init.shared.b64 [%0], 12;" :: "r"(mb0 + s * 16 + 8) : "memory");
        }
    }
    __syncthreads();  // only block-wide barrier

    if (wid == 12) {
        // Producer. pe starts at 1 (flipped at wrap after chunk NST-1 so the
        // first recycle-wait sees parity 0 = chunk-0 consumption).
        const __half* pA = g_Zh + (size_t)brow * FF;
        const __half* pB = g_Yh + (size_t)bcol * FF;
        int s = 0, pe = 1;
        for (int c = 0; c < NCH; c++) {
            if (c >= NST) mbar_wait(mb0 + s * 16 + 8, (uint32_t)pe);  // empty[s]
            uint32_t stagebase = smem + s * STAGE_B;
            {
                const __half* sb = pA + c * 32;
#pragma unroll
                for (int j = 0; j < 24; j++) {  // A: 192 rows, 768 16B units
                    int idx = lane + j * 32;
                    int r = idx >> 2, ck = idx & 3;
                    const void* src = sb + (size_t)r * FF + ck * 8;
                    uint32_t dst = stagebase + swz(r, ck);
                    asm volatile("cp.async.cg.shared.global [%0], [%1], 16;"
                                 :: "r"(dst), "l"(src));
                }
            }
            {
                const __half* sb = pB + c * 32;
#pragma unroll
                for (int j = 0; j < 16; j++) {  // B: 128 rows, 512 16B units
                    int idx = lane + j * 32;
                    int r = idx >> 2, ck = idx & 3;
                    const void* src = sb + (size_t)r * FF + ck * 8;
                    uint32_t dst = stagebase + OFF_B + swz(r, ck);
                    asm volatile("cp.async.cg.shared.global [%0], [%1], 16;"
                                 :: "r"(dst), "l"(src));
                }
            }
            asm volatile("cp.async.mbarrier.arrive.noinc.shared.b64 [%0];"
                         :: "r"(mb0 + s * 16) : "memory");
            s++; if (s == NST) { s = 0; pe ^= 1; }
        }
        return;
    }

    // Consumers: 12 warps, 32x64 tiles (warp_m 0..5, warp_n 0..1).
    int warp_m = wid % 6;
    int warp_n = wid / 6;

    float acc[2][8][4];
#pragma unroll
    for (int i = 0; i < 2; i++)
#pragma unroll
        for (int j = 0; j < 8; j++)
#pragma unroll
            for (int v = 0; v < 4; v++) acc[i][j][v] = 0.f;

    int a_r = warp_m * 32 + (lane & 15);
    int b_r = warp_n * 64 + (lane & 15);
    int csel = lane >> 4;

    uint32_t fa[2][4], fb[4][4];

    int st = 0, pf = 0;
    for (int c = 0; c < NCH; c++) {
        mbar_wait(mb0 + st * 16, (uint32_t)pf);  // full[st]
        uint32_t buf = smem + st * STAGE_B;

#pragma unroll
        for (int ks = 0; ks < 2; ks++) {
#pragma unroll
            for (int i = 0; i < 2; i++)
                ldsm_x4(fa[i], buf + swz(a_r + i * 16, ks * 2 + csel));
#pragma unroll
            for (int g = 0; g < 4; g++)
                ldsm_x4(fb[g], buf + OFF_B + swz(b_r + g * 16, ks * 2 + csel));
#pragma unroll
            for (int i = 0; i < 2; i++)
#pragma unroll
                for (int jj = 0; jj < 8; jj++) {
                    int g = jj >> 1, w = jj & 1;
                    mma16816(acc[i][jj], fa[i], fb[g][w], fb[g][2 + w]);
                }
        }

        if (lane == 0)
            asm volatile("mbarrier.arrive.shared.b64 _, [%0];"
                         :: "r"(mb0 + st * 16 + 8) : "memory");  // empty[st]
        st++; if (st == NST) { st = 0; pf ^= 1; }
    }

    // Epilogue: threshold filter. Definite gt counted; near-threshold cols
    // pushed for exact fp32 rescore.
#pragma unroll
    for (int i = 0; i < 2; i++) {
#pragma unroll
        for (int h = 0; h < 2; h++) {
            int row = brow + warp_m * 32 + i * 16 + (lane >> 2) + h * 8;
            float sl = g_simL[row];
            int lab = g_labels[row];
            int gt = 0;
#pragma unroll
            for (int jj = 0; jj < 8; jj++) {
#pragma unroll
                for (int w = 0; w < 2; w++) {
                    int col = bcol + warp_n * 64 + jj * 8 + (lane & 3) * 2 + w;
                    float v = acc[i][jj][h * 2 + w];
                    if (col < SS && col != lab) {
                        if (v > sl + DELTA) gt++;
                        else if (v >= sl - DELTA) {
                            int idx = atomicAdd(&g_ambcnt[row], 1);
                            if (idx < AMAX) g_ambcol[(size_t)row * AMAX + idx] = col;
                        }
                    }
                }
            }
            gt += __shfl_xor_sync(0xffffffffu, gt, 1);
            gt += __shfl_xor_sync(0xffffffffu, gt, 2);
            if ((lane & 3) == 0 && gt) atomicAdd(&g_gt[row], gt);
        }
    }
}

// ---------------------------------------------------------------------------
// Launch 5: exact fp32 rescore of ambiguous cols + per-row finalize.
// One block per row; the block fully owns its row's rank and hit counting.
__global__ __launch_bounds__(512) void rescore_kernel(const float* __restrict__ Z,
                                                      const float* __restrict__ Y) {
    int row = blockIdx.x;
    int tid = threadIdx.x, lane = tid & 31, wrp = tid >> 5;
    int cnt = g_ambcnt[row];

    if (cnt == 0) {  // rank already final
        if (tid == 0) {
            int r = g_gt[row];
            if (r < 1) atomicAdd(&g_hit[0], 1);
            if (r < 5) atomicAdd(&g_hit[1], 1);
        }
        return;
    }

    bool ovf = cnt > AMAX;
    int n = ovf ? SS : cnt;

    __shared__ float zs[FF];
    __shared__ int s_gt;
    if (tid == 0) s_gt = 0;
    const float* z = Z + (size_t)row * FF;
    for (int c = tid * 4; c < FF; c += 2048)
        *(float4*)(zs + c) = *(const float4*)(z + c);
    __syncthreads();

    float sl = g_simL[row];
    int lab = g_labels[row];
    float zn = g_Znorm[row];

    int gt = 0;
    for (int k = wrp; k < n; k += 16) {
        int col = ovf ? k : g_ambcol[(size_t)row * AMAX + k];
        if (col == lab || col >= SS) continue;
        const float* y = Y + (size_t)col * FF;
        float s = 0.f;
#pragma unroll 4
        for (int c = lane * 4; c < FF; c += 128) {
            float4 a = *(const float4*)(zs + c);
            float4 b = *(const float4*)(y + c);
            s += a.x * b.x + a.y * b.y + a.z * b.z + a.w * b.w;
        }
        for (int o = 16; o > 0; o >>= 1) s += __shfl_xor_sync(0xffffffffu, s, o);
        if (lane == 0) {
            float v = s / (zn * g_Ynorm[col]);
            if (v > sl) gt++;
            else if (v == sl && col < lab) gt++;
        }
    }
    if (lane == 0 && gt) atomicAdd(&s_gt, gt);
    __syncthreads();
    if (tid == 0) {
        int r = ovf ? s_gt : (g_gt[row] + s_gt);  // ovf: full recount replaces
        if (r < 1) atomicAdd(&g_hit[0], 1);
        if (r < 5) atomicAdd(&g_hit[1], 1);
    }
}

// ---------------------------------------------------------------------------
__global__ void writeout_kernel(float* __restrict__ out) {
    out[0] = (float)g_hit[0] / (float)BB;
    out[1] = (float)g_hit[1] / (float)BB;
}

// ---------------------------------------------------------------------------
extern "C" void kernel_launch(void* const* d_in, const int* in_sizes, int n_in,
                              void* d_out, int out_size) {
    (void)in_sizes; (void)n_in; (void)out_size;
    const float* Z    = (const float*)d_in[0];
    const int*   yidx = (const int*)d_in[1];
    const float* Y    = (const float*)d_in[2];
    const int*   test = (const int*)d_in[3];
    float* out = (float*)d_out;

    cudaFuncSetAttribute(gemm_count_kernel,
                         cudaFuncAttributeMaxDynamicSharedMemorySize, SMEM_DYN);

    init_scatter_kernel<<<(BB + 255) / 256, 256>>>(test);      // launch 1
    norm_split_kernel<<<BB + SPAD, 128>>>(Z, Y);               // launch 2
    labels_simL_kernel<<<BB, 128>>>(Z, Y, yidx);               // launch 3

    dim3 grid(SPAD / 128, BB / 192);
    gemm_count_kernel<<<grid, 416, SMEM_DYN>>>();              // launch 4 (ncu target)

    rescore_kernel<<<BB, 512>>>(Z, Y);                         // launch 5 (+finalize)
    writeout_kernel<<<1, 1>>>(out);                            // launch 6
}

// round 17
// speedup vs baseline: 1.4583x; 1.1413x over previous
#include <cuda_runtime.h>
#include <cuda_fp16.h>
#include <cstdint>

// Problem dimensions (fixed by setup_inputs)
#define BB 9600      // batch rows (Z)
#define SS 2400      // candidate rows (Y)
#define SPAD 2432    // S padded to multiple of 128
#define FF 4096      // feature dim
#define NCH (FF / 32)  // 32-elem K chunks for GEMM

#define AMAX 512         // ambiguous-col capacity per row (overflow -> full recount)
#define DELTA 1e-4f      // >=12-sigma filter window for fp16 sims

// ---------------------------------------------------------------------------
// Scratch (device globals: allocation-free rule). fp16 high parts.
__device__ __half g_Zh[(size_t)BB * FF];
__device__ __half g_Yh[(size_t)SPAD * FF];
__device__ float g_Znorm[BB];
__device__ float g_Ynorm[SS];
__device__ float g_simL[BB];
__device__ int   g_labels[BB];
__device__ int   g_inv[SS];
__device__ int   g_gt[BB];       // definite counts from filter
__device__ int   g_ambcnt[BB];
__device__ int   g_ambcol[(size_t)BB * AMAX];
__device__ int   g_hit[2];

// ---------------------------------------------------------------------------
// Launch 1: zero counters + scatter inverse map (test values unique per spec).
__global__ void init_scatter_kernel(const int* __restrict__ test) {
    int i = blockIdx.x * blockDim.x + threadIdx.x;
    if (i < BB) { g_gt[i] = 0; g_ambcnt[i] = 0; }
    if (i < 2)  g_hit[i] = 0;
    if (i < SS) {
        int v = test[i];
        if (v >= 0 && v < SS) g_inv[v] = i;
    }
}

__device__ __forceinline__ uint32_t pack_h2(__half a, __half b) {
    __half2 t = __halves2half2(a, b);
    return *reinterpret_cast<uint32_t*>(&t);
}

// Launch 2: normalize row -> fp16 high part + fp32 norm. Covers Z and Y.
__global__ void norm_split_kernel(const float* __restrict__ Zsrc,
                                  const float* __restrict__ Ysrc) {
    int row = blockIdx.x;
    int tid = threadIdx.x;  // 128 threads
    const float* src;
    __half* H;
    int which;
    if (row < BB) {
        src = Zsrc; H = g_Zh; which = 0;
    } else {
        row -= BB;
        src = Ysrc; H = g_Yh; which = 1;
    }
    size_t base = (size_t)row * FF;

    if (which == 1 && row >= SS) {  // zero padding rows (Y only)
        for (int j = 0; j < 8; j++)
            *(uint2*)(H + base + tid * 4 + j * 512) = make_uint2(0, 0);
        return;
    }

    float4 v[8];
    float s = 0.f;
#pragma unroll
    for (int j = 0; j < 8; j++) {
        v[j] = *(const float4*)(src + base + tid * 4 + j * 512);
        s += v[j].x * v[j].x + v[j].y * v[j].y + v[j].z * v[j].z + v[j].w * v[j].w;
    }
    for (int o = 16; o > 0; o >>= 1) s += __shfl_xor_sync(0xffffffffu, s, o);
    __shared__ float red[4];
    __shared__ float s_n;
    if ((tid & 31) == 0) red[tid >> 5] = s;
    __syncthreads();
    if (tid == 0) {
        float t = red[0] + red[1] + red[2] + red[3];
        s_n = fmaxf(sqrtf(t), 1e-8f);
        if (which == 0) g_Znorm[row] = s_n;
        else            g_Ynorm[row] = s_n;
    }
    __syncthreads();
    float n = s_n;

#pragma unroll
    for (int j = 0; j < 8; j++) {
        size_t off = base + tid * 4 + j * 512;
        float x[4] = {v[j].x / n, v[j].y / n, v[j].z / n, v[j].w / n};
        __half h[4];
#pragma unroll
        for (int e = 0; e < 4; e++) h[e] = __float2half(x[e]);
        *(uint2*)(H + off) = make_uint2(pack_h2(h[0], h[1]), pack_h2(h[2], h[3]));
    }
}

// Launch 3: labels[i] = inv[yidx[i]]; simL[i] = cos-sim(Z[i], Y[lab]) in fp32.
__global__ void labels_simL_kernel(const float* __restrict__ Z,
                                   const float* __restrict__ Y,
                                   const int* __restrict__ yidx) {
    int i = blockIdx.x;
    int tid = threadIdx.x;  // 128
    __shared__ int s_lab;
    if (tid == 0) {
        int v = yidx[i];
        int lab = 0;
        if (v >= 0 && v < SS) lab = g_inv[v];
        g_labels[i] = lab;
        s_lab = lab;
    }
    __syncthreads();
    int lab = s_lab;
    const float* z = Z + (size_t)i * FF;
    const float* y = Y + (size_t)lab * FF;
    float s = 0.f;
    for (int c = tid * 4; c < FF; c += 512) {
        float4 a = *(const float4*)(z + c);
        float4 b = *(const float4*)(y + c);
        s += a.x * b.x + a.y * b.y + a.z * b.z + a.w * b.w;
    }
    for (int o = 16; o > 0; o >>= 1) s += __shfl_xor_sync(0xffffffffu, s, o);
    __shared__ float red[4];
    if ((tid & 31) == 0) red[tid >> 5] = s;
    __syncthreads();
    if (tid == 0) {
        float t = red[0] + red[1] + red[2] + red[3];
        g_simL[i] = t / (g_Znorm[i] * g_Ynorm[lab]);
    }
}

// ---------------------------------------------------------------------------
// Launch 4: warp-specialized fp16 HMMA filter GEMM + threshold epilogue.
// 192x128 CTA tile, BK=32, 8-stage mbarrier ring, 12 consumer warps
// + 1 producer warp (416 threads).
#define A_TILE_B 12288               // 192 rows x 64B
#define B_TILE_B 8192                // 128 rows x 64B
#define STAGE_B  (A_TILE_B + B_TILE_B)  // 20 KB
#define OFF_B    A_TILE_B
#define NST 8
#define SMEM_DYN (NST * STAGE_B)     // 160 KB

// 64B-row swizzle: row r, 16B-chunk c (0..3)
__device__ __forceinline__ uint32_t swz(int r, int c) {
    return (uint32_t)(r * 64 + ((c ^ ((r >> 1) & 3)) << 4));
}

static __device__ __forceinline__ uint32_t cvta_s(const void* p) {
    uint32_t a;
    asm("{ .reg .u64 t; cvta.to.shared.u64 t, %1; cvt.u32.u64 %0, t; }" : "=r"(a) : "l"(p));
    return a;
}

__device__ __forceinline__ void ldsm_x4(uint32_t* r, uint32_t addr) {
    asm volatile("ldmatrix.sync.aligned.m8n8.x4.shared.b16 {%0,%1,%2,%3}, [%4];"
                 : "=r"(r[0]), "=r"(r[1]), "=r"(r[2]), "=r"(r[3]) : "r"(addr));
}

__device__ __forceinline__ void mma16816(float* c, const uint32_t* a, uint32_t b0, uint32_t b1) {
    asm volatile(
        "mma.sync.aligned.m16n8k16.row.col.f32.f16.f16.f32 "
        "{%0,%1,%2,%3}, {%4,%5,%6,%7}, {%8,%9}, {%0,%1,%2,%3};"
        : "+f"(c[0]), "+f"(c[1]), "+f"(c[2]), "+f"(c[3])
        : "r"(a[0]), "r"(a[1]), "r"(a[2]), "r"(a[3]), "r"(b0), "r"(b1));
}

__device__ __forceinline__ void mbar_wait(uint32_t mbar, uint32_t parity) {
    uint32_t done;
    asm volatile(
        "{\n\t.reg .pred p;\n\t"
        "mbarrier.try_wait.parity.shared.b64 p, [%1], %2;\n\t"
        "selp.b32 %0, 1, 0, p;\n\t}"
        : "=r"(done) : "r"(mbar), "r"(parity) : "memory");
    if (!done) {
        asm volatile(
            "{\n\t.reg .pred P1;\n\t"
            "WL_%=:\n\t"
            "mbarrier.try_wait.parity.shared.b64 P1, [%0], %1;\n\t"
            "@P1 bra.uni WD_%=;\n\t"
            "bra.uni WL_%=;\n\t"
            "WD_%=:\n\t}"
            :: "r"(mbar), "r"(parity) : "memory");
    }
}

extern __shared__ char dsm[];

__global__ __launch_bounds__(416, 1) void gemm_count_kernel() {
    __shared__ __align__(8) unsigned long long s_mb[2 * NST];
    int tid = threadIdx.x;
    int lane = tid & 31, wid = tid >> 5;
    int brow = blockIdx.y * 192;
    int bcol = blockIdx.x * 128;
    uint32_t smem = cvta_s(dsm);
    uint32_t mb0 = cvta_s(&s_mb[0]);

    if (tid == 0) {
#pragma unroll
        for (int s = 0; s < NST; s++) {
            asm volatile("mbarrier.init.shared.b64 [%0], 32;" :: "r"(mb0 + s * 16) : "memory");
            asm volatile("mbarrier.init.shared.b64 [%0], 12;" :: "r"(mb0 + s * 16 + 8) : "memory");
        }
    }
    __syncthreads();  // only block-wide barrier

    if (wid == 12) {
        // Producer. pe starts at 1 (flipped at wrap after chunk NST-1 so the
        // first recycle-wait sees parity 0 = chunk-0 consumption).
        const __half* pA = g_Zh + (size_t)brow * FF;
        const __half* pB = g_Yh + (size_t)bcol * FF;
        int s = 0, pe = 1;
        for (int c = 0; c < NCH; c++) {
            if (c >= NST) mbar_wait(mb0 + s * 16 + 8, (uint32_t)pe);  // empty[s]
            uint32_t stagebase = smem + s * STAGE_B;
            {
                const __half* sb = pA + c * 32;
#pragma unroll
                for (int j = 0; j < 24; j++) {  // A: 192 rows, 768 16B units
                    int idx = lane + j * 32;
                    int r = idx >> 2, ck = idx & 3;
                    const void* src = sb + (size_t)r * FF + ck * 8;
                    uint32_t dst = stagebase + swz(r, ck);
                    asm volatile("cp.async.cg.shared.global [%0], [%1], 16;"
                                 :: "r"(dst), "l"(src));
                }
            }
            {
                const __half* sb = pB + c * 32;
#pragma unroll
                for (int j = 0; j < 16; j++) {  // B: 128 rows, 512 16B units
                    int idx = lane + j * 32;
                    int r = idx >> 2, ck = idx & 3;
                    const void* src = sb + (size_t)r * FF + ck * 8;
                    uint32_t dst = stagebase + OFF_B + swz(r, ck);
                    asm volatile("cp.async.cg.shared.global [%0], [%1], 16;"
                                 :: "r"(dst), "l"(src));
                }
            }
            asm volatile("cp.async.mbarrier.arrive.noinc.shared.b64 [%0];"
                         :: "r"(mb0 + s * 16) : "memory");
            s++; if (s == NST) { s = 0; pe ^= 1; }
        }
        return;
    }

    // Consumers: 12 warps, 32x64 tiles (warp_m 0..5, warp_n 0..1).
    int warp_m = wid % 6;
    int warp_n = wid / 6;

    float acc[2][8][4];
#pragma unroll
    for (int i = 0; i < 2; i++)
#pragma unroll
        for (int j = 0; j < 8; j++)
#pragma unroll
            for (int v = 0; v < 4; v++) acc[i][j][v] = 0.f;

    int a_r = warp_m * 32 + (lane & 15);
    int b_r = warp_n * 64 + (lane & 15);
    int csel = lane >> 4;

    uint32_t fa[2][4], fb[4][4];

    int st = 0, pf = 0;
    for (int c = 0; c < NCH; c++) {
        mbar_wait(mb0 + st * 16, (uint32_t)pf);  // full[st]
        uint32_t buf = smem + st * STAGE_B;

#pragma unroll
        for (int ks = 0; ks < 2; ks++) {
#pragma unroll
            for (int i = 0; i < 2; i++)
                ldsm_x4(fa[i], buf + swz(a_r + i * 16, ks * 2 + csel));
#pragma unroll
            for (int g = 0; g < 4; g++)
                ldsm_x4(fb[g], buf + OFF_B + swz(b_r + g * 16, ks * 2 + csel));
#pragma unroll
            for (int i = 0; i < 2; i++)
#pragma unroll
                for (int jj = 0; jj < 8; jj++) {
                    int g = jj >> 1, w = jj & 1;
                    mma16816(acc[i][jj], fa[i], fb[g][w], fb[g][2 + w]);
                }
        }

        if (lane == 0)
            asm volatile("mbarrier.arrive.shared.b64 _, [%0];"
                         :: "r"(mb0 + st * 16 + 8) : "memory");  // empty[st]
        st++; if (st == NST) { st = 0; pf ^= 1; }
    }

    // Epilogue: threshold filter. Definite gt counted; near-threshold cols
    // pushed for exact fp32 rescore.
#pragma unroll
    for (int i = 0; i < 2; i++) {
#pragma unroll
        for (int h = 0; h < 2; h++) {
            int row = brow + warp_m * 32 + i * 16 + (lane >> 2) + h * 8;
            float sl = g_simL[row];
            int lab = g_labels[row];
            int gt = 0;
#pragma unroll
            for (int jj = 0; jj < 8; jj++) {
#pragma unroll
                for (int w = 0; w < 2; w++) {
                    int col = bcol + warp_n * 64 + jj * 8 + (lane & 3) * 2 + w;
                    float v = acc[i][jj][h * 2 + w];
                    if (col < SS && col != lab) {
                        if (v > sl + DELTA) gt++;
                        else if (v >= sl - DELTA) {
                            int idx = atomicAdd(&g_ambcnt[row], 1);
                            if (idx < AMAX) g_ambcol[(size_t)row * AMAX + idx] = col;
                        }
                    }
                }
            }
            gt += __shfl_xor_sync(0xffffffffu, gt, 1);
            gt += __shfl_xor_sync(0xffffffffu, gt, 2);
            if ((lane & 3) == 0 && gt) atomicAdd(&g_gt[row], gt);
        }
    }
}

// ---------------------------------------------------------------------------
// Launch 5: exact fp32 rescore of ambiguous cols + per-row finalize.
// KEY: a row with >= 5 DEFINITE gt cols already has rank >= 5 => misses both
// top-1 and top-5 regardless of ambiguous outcomes -> no rescore needed.
// Expected rescoring rows: P(rank < ~14) ~ 0.6% of 9600.
__global__ __launch_bounds__(512) void rescore_kernel(const float* __restrict__ Z,
                                                      const float* __restrict__ Y) {
    int row = blockIdx.x;
    int tid = threadIdx.x, lane = tid & 31, wrp = tid >> 5;
    int cnt = g_ambcnt[row];
    int basegt = g_gt[row];

    if (cnt == 0 || basegt >= 5) {  // rank final (or provably >= 5: both miss)
        if (tid == 0) {
            int r = basegt;
            if (r < 1) atomicAdd(&g_hit[0], 1);
            if (r < 5) atomicAdd(&g_hit[1], 1);
        }
        return;
    }

    bool ovf = cnt > AMAX;
    int n = ovf ? SS : cnt;

    __shared__ float zs[FF];
    __shared__ int s_gt;
    if (tid == 0) s_gt = 0;
    const float* z = Z + (size_t)row * FF;
    for (int c = tid * 4; c < FF; c += 2048)
        *(float4*)(zs + c) = *(const float4*)(z + c);
    __syncthreads();

    float sl = g_simL[row];
    int lab = g_labels[row];
    float zn = g_Znorm[row];

    int gt = 0;
    for (int k = wrp; k < n; k += 16) {
        int col = ovf ? k : g_ambcol[(size_t)row * AMAX + k];
        if (col == lab || col >= SS) continue;
        const float* y = Y + (size_t)col * FF;
        float s = 0.f;
#pragma unroll 4
        for (int c = lane * 4; c < FF; c += 128) {
            float4 a = *(const float4*)(zs + c);
            float4 b = *(const float4*)(y + c);
            s += a.x * b.x + a.y * b.y + a.z * b.z + a.w * b.w;
        }
        for (int o = 16; o > 0; o >>= 1) s += __shfl_xor_sync(0xffffffffu, s, o);
        if (lane == 0) {
            float v = s / (zn * g_Ynorm[col]);
            if (v > sl) gt++;
            else if (v == sl && col < lab) gt++;
        }
    }
    if (lane == 0 && gt) atomicAdd(&s_gt, gt);
    __syncthreads();
    if (tid == 0) {
        int r = ovf ? s_gt : (basegt + s_gt);  // ovf: full recount replaces
        if (r < 1) atomicAdd(&g_hit[0], 1);
        if (r < 5) atomicAdd(&g_hit[1], 1);
    }
}

// ---------------------------------------------------------------------------
__global__ void writeout_kernel(float* __restrict__ out) {
    out[0] = (float)g_hit[0] / (float)BB;
    out[1] = (float)g_hit[1] / (float)BB;
}

// ---------------------------------------------------------------------------
extern "C" void kernel_launch(void* const* d_in, const int* in_sizes, int n_in,
                              void* d_out, int out_size) {
    (void)in_sizes; (void)n_in; (void)out_size;
    const float* Z    = (const float*)d_in[0];
    const int*   yidx = (const int*)d_in[1];
    const float* Y    = (const float*)d_in[2];
    const int*   test = (const int*)d_in[3];
    float* out = (float*)d_out;

    cudaFuncSetAttribute(gemm_count_kernel,
                         cudaFuncAttributeMaxDynamicSharedMemorySize, SMEM_DYN);

    init_scatter_kernel<<<(BB + 255) / 256, 256>>>(test);      // launch 1
    norm_split_kernel<<<BB + SPAD, 128>>>(Z, Y);               // launch 2
    labels_simL_kernel<<<BB, 128>>>(Z, Y, yidx);               // launch 3

    dim3 grid(SPAD / 128, BB / 192);
    gemm_count_kernel<<<grid, 416, SMEM_DYN>>>();              // launch 4 (ncu target)

    rescore_kernel<<<BB, 512>>>(Z, Y);                         // launch 5 (+finalize)
    writeout_kernel<<<1, 1>>>(out);                            // launch 6
}